// round 8
// baseline (speedup 1.0000x reference)
#include <cuda_runtime.h>
#include <cuda_fp16.h>

// bg: (1, 4, 32, 32, 32, 16) f32   -> d_in[0]
// gm: (1, 1, 128, 128, 128) f32    -> d_in[1]
// out:(1, 4, 128, 128, 128) f32

#define GH 128
#define GWD 128
#define GD 128
#define H 32
#define W 32
#define D 32
#define UP 16
#define TH 4
#define TW 4
#define ROWE 512                       // [z][t] entries per column plane
#define PLANE_E (16 * ROWE)
#define PLANE_BYTES (PLANE_E * 8)      // 65536

#define CH_STRIDE (H*W*D*UP)           // 524288
#define OUT_CH (GH*GWD*GD)             // 2097152

__device__ __forceinline__ __half2 u2h(unsigned int u) {
    __half2 h; *reinterpret_cast<unsigned int*>(&h) = u; return h;
}
__device__ __forceinline__ unsigned int h2u(__half2 h) {
    return *reinterpret_cast<unsigned int*>(&h);
}

__global__ void __launch_bounds__(256, 3)
bgrid_slice_kernel(const float* __restrict__ bg,
                   const float* __restrict__ gm,
                   float* __restrict__ out)
{
    extern __shared__ uint2 S_plane[];           // [col][z][t] fp16x4
    __shared__ uint4 WX3[TH];
    __shared__ uint4 WY3[TW];

    const float sx = 31.0f / 127.0f;
    const int gh0 = blockIdx.y * TH;
    const int gw0 = blockIdx.x * TW;
    const int X = (int)floorf((float)gh0 * sx);
    const int Y = (int)floorf((float)gw0 * sx);
    const int tid = threadIdx.x;

    // ---- phase-2 constants + EARLY gm prefetch (hidden under phase 1) ----
    const int lane = tid & 31;
    const int wq = tid >> 5;                     // warp id 0..7
    const int gd0 = lane * 4;

    int obase[2];
    #pragma unroll
    for (int i = 0; i < 2; i++) {
        int col = wq + 8 * i;
        int gh = gh0 + (col >> 2);
        int gw = gw0 + (col & 3);
        obase[i] = (gh * GWD + gw) * GD + gd0;
    }
    float4 gv0 = *reinterpret_cast<const float4*>(&gm[obase[0]]);
    float4 gv1 = *reinterpret_cast<const float4*>(&gm[obase[1]]);

    // ---- tiny weight tables (3-tap padded, branch-free downstream) ----
    if (tid < 8) {
        int l = tid & 3;
        int base = (tid < 4) ? gh0 : gw0;
        int O = (tid < 4) ? X : Y;
        float c = fminf((float)(base + l) * sx, 31.0f);
        float c0f = floorf(c);
        float f = c - c0f;
        int l0 = (int)c0f - O;                    // 0 or 1
        uint4 w3;
        if (l0 == 0) {
            w3.x = h2u(__float2half2_rn(1.f - f));
            w3.y = h2u(__float2half2_rn(f));
            w3.z = 0u;
        } else {
            w3.x = 0u;
            w3.y = h2u(__float2half2_rn(1.f - f));
            w3.z = h2u(__float2half2_rn(f));
        }
        w3.w = 0u;
        if (tid < 4) WX3[l] = w3; else WY3[l] = w3;
    }
    __syncthreads();

    // ---- phase 1: zt-pair per thread, float2 loads, register blend, STS.128 ----
    {
        const int zt0 = tid * 2;

        int rowbase[9];
        #pragma unroll
        for (int r = 0; r < 9; r++) {
            int a = r / 3, b = r - a * 3;
            int gx = min(X + a, H - 1);
            int gy = min(Y + b, W - 1);
            rowbase[r] = (gx * W + gy) * ROWE;
        }

        uint2 Rlo[9], Rhi[9];
        #pragma unroll
        for (int r = 0; r < 9; r++) {
            int idx = rowbase[r] + zt0;
            float2 c0 = *reinterpret_cast<const float2*>(&bg[idx]);
            float2 c1 = *reinterpret_cast<const float2*>(&bg[idx + CH_STRIDE]);
            float2 c2 = *reinterpret_cast<const float2*>(&bg[idx + 2 * CH_STRIDE]);
            float2 c3 = *reinterpret_cast<const float2*>(&bg[idx + 3 * CH_STRIDE]);
            Rlo[r].x = h2u(__floats2half2_rn(c0.x, c1.x));
            Rlo[r].y = h2u(__floats2half2_rn(c2.x, c3.x));
            Rhi[r].x = h2u(__floats2half2_rn(c0.y, c1.y));
            Rhi[r].y = h2u(__floats2half2_rn(c2.y, c3.y));
        }

        #pragma unroll
        for (int lw = 0; lw < 4; lw++) {
            uint4 wy = WY3[lw];
            __half2 v0 = u2h(wy.x), v1 = u2h(wy.y), v2 = u2h(wy.z);
            uint2 Tlo[3], Thi[3];
            #pragma unroll
            for (int a = 0; a < 3; a++) {
                __half2 t01 = __hmul2(v0, u2h(Rlo[a*3 + 0].x));
                t01 = __hfma2(v1, u2h(Rlo[a*3 + 1].x), t01);
                t01 = __hfma2(v2, u2h(Rlo[a*3 + 2].x), t01);
                __half2 t23 = __hmul2(v0, u2h(Rlo[a*3 + 0].y));
                t23 = __hfma2(v1, u2h(Rlo[a*3 + 1].y), t23);
                t23 = __hfma2(v2, u2h(Rlo[a*3 + 2].y), t23);
                Tlo[a].x = h2u(t01); Tlo[a].y = h2u(t23);
                t01 = __hmul2(v0, u2h(Rhi[a*3 + 0].x));
                t01 = __hfma2(v1, u2h(Rhi[a*3 + 1].x), t01);
                t01 = __hfma2(v2, u2h(Rhi[a*3 + 2].x), t01);
                t23 = __hmul2(v0, u2h(Rhi[a*3 + 0].y));
                t23 = __hfma2(v1, u2h(Rhi[a*3 + 1].y), t23);
                t23 = __hfma2(v2, u2h(Rhi[a*3 + 2].y), t23);
                Thi[a].x = h2u(t01); Thi[a].y = h2u(t23);
            }
            #pragma unroll
            for (int lh = 0; lh < 4; lh++) {
                uint4 wx = WX3[lh];
                __half2 w0 = u2h(wx.x), w1 = u2h(wx.y), w2 = u2h(wx.z);
                __half2 a01 = __hmul2(w0, u2h(Tlo[0].x));
                a01 = __hfma2(w1, u2h(Tlo[1].x), a01);
                a01 = __hfma2(w2, u2h(Tlo[2].x), a01);
                __half2 a23 = __hmul2(w0, u2h(Tlo[0].y));
                a23 = __hfma2(w1, u2h(Tlo[1].y), a23);
                a23 = __hfma2(w2, u2h(Tlo[2].y), a23);
                __half2 b01 = __hmul2(w0, u2h(Thi[0].x));
                b01 = __hfma2(w1, u2h(Thi[1].x), b01);
                b01 = __hfma2(w2, u2h(Thi[2].x), b01);
                __half2 b23 = __hmul2(w0, u2h(Thi[0].y));
                b23 = __hfma2(w1, u2h(Thi[1].y), b23);
                b23 = __hfma2(w2, u2h(Thi[2].y), b23);
                uint4 q;
                q.x = h2u(a01); q.y = h2u(a23);
                q.z = h2u(b01); q.w = h2u(b23);
                *reinterpret_cast<uint4*>(&S_plane[(lh*4 + lw) * ROWE + zt0]) = q;
            }
        }
    }
    __syncthreads();

    // ---- phase 2: gd-quad per lane, one column per warp per iteration ----
    // hoisted z-chains for the 4 gd values (iteration-invariant)
    int z0o[4], z1o[4];
    float fzv[4], wza[4];
    #pragma unroll
    for (int j = 0; j < 4; j++) {
        float zc = fminf((float)(gd0 + j) * sx, 31.0f);
        float z0f = floorf(zc);
        float fz = zc - z0f;
        int z0 = (int)z0f;
        int z1 = min(z0 + 1, D - 1);
        z0o[j] = z0 * 16;
        z1o[j] = z1 * 16;
        fzv[j] = fz;
        wza[j] = 1.f - fz;
    }

    #pragma unroll
    for (int i = 0; i < 2; i++) {
        int col = wq + 8 * i;
        const uint2* P = S_plane + col * ROWE;
        float4 g4 = (i == 0) ? gv0 : gv1;
        float tg[4] = { g4.x, g4.y, g4.z, g4.w };

        float acc[4][4];
        #pragma unroll
        for (int j = 0; j < 4; j++) {
            float t = fminf(fmaxf(tg[j] * 15.0f, 0.0f), 15.0f);
            float t0f = floorf(t);
            float ft = t - t0f;
            int t0 = (int)t0f;
            int t1 = min(t0 + 1, UP - 1);

            uint2 e00 = P[z0o[j] + t0];
            uint2 e01 = P[z0o[j] + t1];
            uint2 e10 = P[z1o[j] + t0];
            uint2 e11 = P[z1o[j] + t1];

            float w00 = wza[j] * (1.f - ft);
            float w01 = wza[j] * ft;
            float w10 = fzv[j] * (1.f - ft);
            float w11 = fzv[j] * ft;

            float2 p01, p23;
            p01 = __half22float2(u2h(e00.x)); p23 = __half22float2(u2h(e00.y));
            acc[j][0] = p01.x * w00; acc[j][1] = p01.y * w00;
            acc[j][2] = p23.x * w00; acc[j][3] = p23.y * w00;
            p01 = __half22float2(u2h(e01.x)); p23 = __half22float2(u2h(e01.y));
            acc[j][0] = fmaf(p01.x, w01, acc[j][0]); acc[j][1] = fmaf(p01.y, w01, acc[j][1]);
            acc[j][2] = fmaf(p23.x, w01, acc[j][2]); acc[j][3] = fmaf(p23.y, w01, acc[j][3]);
            p01 = __half22float2(u2h(e10.x)); p23 = __half22float2(u2h(e10.y));
            acc[j][0] = fmaf(p01.x, w10, acc[j][0]); acc[j][1] = fmaf(p01.y, w10, acc[j][1]);
            acc[j][2] = fmaf(p23.x, w10, acc[j][2]); acc[j][3] = fmaf(p23.y, w10, acc[j][3]);
            p01 = __half22float2(u2h(e11.x)); p23 = __half22float2(u2h(e11.y));
            acc[j][0] = fmaf(p01.x, w11, acc[j][0]); acc[j][1] = fmaf(p01.y, w11, acc[j][1]);
            acc[j][2] = fmaf(p23.x, w11, acc[j][2]); acc[j][3] = fmaf(p23.y, w11, acc[j][3]);
        }

        #pragma unroll
        for (int c = 0; c < 4; c++) {
            float4 o = make_float4(acc[0][c], acc[1][c], acc[2][c], acc[3][c]);
            *reinterpret_cast<float4*>(&out[obase[i] + c * OUT_CH]) = o;
        }
    }
}

extern "C" void kernel_launch(void* const* d_in, const int* in_sizes, int n_in,
                              void* d_out, int out_size)
{
    const float* bg = (const float*)d_in[0];
    const float* gm = (const float*)d_in[1];
    float* out = (float*)d_out;

    cudaFuncSetAttribute(bgrid_slice_kernel,
                         cudaFuncAttributeMaxDynamicSharedMemorySize, PLANE_BYTES);

    dim3 grid(GWD / TW, GH / TH);   // 32 x 32 = 1024 blocks
    bgrid_slice_kernel<<<grid, 256, PLANE_BYTES>>>(bg, gm, out);
}

// round 9
// speedup vs baseline: 1.0031x; 1.0031x over previous
#include <cuda_runtime.h>
#include <cuda_fp16.h>

// bg: (1, 4, 32, 32, 32, 16) f32   -> d_in[0]
// gm: (1, 1, 128, 128, 128) f32    -> d_in[1]
// out:(1, 4, 128, 128, 128) f32

#define GH 128
#define GWD 128
#define GD 128
#define H 32
#define W 32
#define D 32
#define UP 16
#define TH 4
#define TW 4
#define ROWE 512                       // [z][t] entries per column plane
#define PLANE_E (16 * ROWE)
#define PLANE_BYTES (PLANE_E * 8)      // 65536

#define CH_STRIDE (H*W*D*UP)           // 524288
#define OUT_CH (GH*GWD*GD)             // 2097152

__device__ __forceinline__ __half2 u2h(unsigned int u) {
    __half2 h; *reinterpret_cast<unsigned int*>(&h) = u; return h;
}
__device__ __forceinline__ unsigned int h2u(__half2 h) {
    return *reinterpret_cast<unsigned int*>(&h);
}

__global__ void __launch_bounds__(256, 3)
bgrid_slice_kernel(const float* __restrict__ bg,
                   const float* __restrict__ gm,
                   float* __restrict__ out)
{
    extern __shared__ uint2 S_plane[];           // [col][z][t] fp16x4
    __shared__ uint4 WX3[TH];
    __shared__ uint4 WY3[TW];

    const float sx = 31.0f / 127.0f;
    const int gh0 = blockIdx.y * TH;
    const int gw0 = blockIdx.x * TW;
    const int X = (int)floorf((float)gh0 * sx);
    const int Y = (int)floorf((float)gw0 * sx);
    const int tid = threadIdx.x;

    // ---- phase-2 constants + EARLY gm prefetch (hidden under phase 1) ----
    const int lane = tid & 31;
    const int wq = tid >> 5;                     // warp id 0..7
    const int gd0 = lane * 4;

    int obase[2];
    #pragma unroll
    for (int i = 0; i < 2; i++) {
        int col = wq + 8 * i;
        int gh = gh0 + (col >> 2);
        int gw = gw0 + (col & 3);
        obase[i] = (gh * GWD + gw) * GD + gd0;
    }
    float4 gv0 = *reinterpret_cast<const float4*>(&gm[obase[0]]);
    float4 gv1 = *reinterpret_cast<const float4*>(&gm[obase[1]]);

    // ---- tiny weight tables (3-tap padded, branch-free downstream) ----
    if (tid < 8) {
        int l = tid & 3;
        int base = (tid < 4) ? gh0 : gw0;
        int O = (tid < 4) ? X : Y;
        float c = fminf((float)(base + l) * sx, 31.0f);
        float c0f = floorf(c);
        float f = c - c0f;
        int l0 = (int)c0f - O;                    // 0 or 1
        uint4 w3;
        if (l0 == 0) {
            w3.x = h2u(__float2half2_rn(1.f - f));
            w3.y = h2u(__float2half2_rn(f));
            w3.z = 0u;
        } else {
            w3.x = 0u;
            w3.y = h2u(__float2half2_rn(1.f - f));
            w3.z = h2u(__float2half2_rn(f));
        }
        w3.w = 0u;
        if (tid < 4) WX3[l] = w3; else WY3[l] = w3;
    }
    __syncthreads();

    // ---- phase 1: zt-pair per thread, float2 loads, register blend, STS.128 ----
    {
        const int zt0 = tid * 2;

        int rowbase[9];
        #pragma unroll
        for (int r = 0; r < 9; r++) {
            int a = r / 3, b = r - a * 3;
            int gx = min(X + a, H - 1);
            int gy = min(Y + b, W - 1);
            rowbase[r] = (gx * W + gy) * ROWE;
        }

        uint2 Rlo[9], Rhi[9];
        #pragma unroll
        for (int r = 0; r < 9; r++) {
            int idx = rowbase[r] + zt0;
            float2 c0 = *reinterpret_cast<const float2*>(&bg[idx]);
            float2 c1 = *reinterpret_cast<const float2*>(&bg[idx + CH_STRIDE]);
            float2 c2 = *reinterpret_cast<const float2*>(&bg[idx + 2 * CH_STRIDE]);
            float2 c3 = *reinterpret_cast<const float2*>(&bg[idx + 3 * CH_STRIDE]);
            Rlo[r].x = h2u(__floats2half2_rn(c0.x, c1.x));
            Rlo[r].y = h2u(__floats2half2_rn(c2.x, c3.x));
            Rhi[r].x = h2u(__floats2half2_rn(c0.y, c1.y));
            Rhi[r].y = h2u(__floats2half2_rn(c2.y, c3.y));
        }

        #pragma unroll
        for (int lw = 0; lw < 4; lw++) {
            uint4 wy = WY3[lw];
            __half2 v0 = u2h(wy.x), v1 = u2h(wy.y), v2 = u2h(wy.z);
            uint2 Tlo[3], Thi[3];
            #pragma unroll
            for (int a = 0; a < 3; a++) {
                __half2 t01 = __hmul2(v0, u2h(Rlo[a*3 + 0].x));
                t01 = __hfma2(v1, u2h(Rlo[a*3 + 1].x), t01);
                t01 = __hfma2(v2, u2h(Rlo[a*3 + 2].x), t01);
                __half2 t23 = __hmul2(v0, u2h(Rlo[a*3 + 0].y));
                t23 = __hfma2(v1, u2h(Rlo[a*3 + 1].y), t23);
                t23 = __hfma2(v2, u2h(Rlo[a*3 + 2].y), t23);
                Tlo[a].x = h2u(t01); Tlo[a].y = h2u(t23);
                t01 = __hmul2(v0, u2h(Rhi[a*3 + 0].x));
                t01 = __hfma2(v1, u2h(Rhi[a*3 + 1].x), t01);
                t01 = __hfma2(v2, u2h(Rhi[a*3 + 2].x), t01);
                t23 = __hmul2(v0, u2h(Rhi[a*3 + 0].y));
                t23 = __hfma2(v1, u2h(Rhi[a*3 + 1].y), t23);
                t23 = __hfma2(v2, u2h(Rhi[a*3 + 2].y), t23);
                Thi[a].x = h2u(t01); Thi[a].y = h2u(t23);
            }
            #pragma unroll
            for (int lh = 0; lh < 4; lh++) {
                uint4 wx = WX3[lh];
                __half2 w0 = u2h(wx.x), w1 = u2h(wx.y), w2 = u2h(wx.z);
                __half2 a01 = __hmul2(w0, u2h(Tlo[0].x));
                a01 = __hfma2(w1, u2h(Tlo[1].x), a01);
                a01 = __hfma2(w2, u2h(Tlo[2].x), a01);
                __half2 a23 = __hmul2(w0, u2h(Tlo[0].y));
                a23 = __hfma2(w1, u2h(Tlo[1].y), a23);
                a23 = __hfma2(w2, u2h(Tlo[2].y), a23);
                __half2 b01 = __hmul2(w0, u2h(Thi[0].x));
                b01 = __hfma2(w1, u2h(Thi[1].x), b01);
                b01 = __hfma2(w2, u2h(Thi[2].x), b01);
                __half2 b23 = __hmul2(w0, u2h(Thi[0].y));
                b23 = __hfma2(w1, u2h(Thi[1].y), b23);
                b23 = __hfma2(w2, u2h(Thi[2].y), b23);
                uint4 q;
                q.x = h2u(a01); q.y = h2u(a23);
                q.z = h2u(b01); q.w = h2u(b23);
                *reinterpret_cast<uint4*>(&S_plane[(lh*4 + lw) * ROWE + zt0]) = q;
            }
        }
    }
    __syncthreads();

    // ---- phase 2: gd-quad per lane, one column per warp per iteration ----
    // hoisted z-chains for the 4 gd values (iteration-invariant)
    int z0o[4], z1o[4];
    float fzv[4], wza[4];
    #pragma unroll
    for (int j = 0; j < 4; j++) {
        float zc = fminf((float)(gd0 + j) * sx, 31.0f);
        float z0f = floorf(zc);
        float fz = zc - z0f;
        int z0 = (int)z0f;
        int z1 = min(z0 + 1, D - 1);
        z0o[j] = z0 * 16;
        z1o[j] = z1 * 16;
        fzv[j] = fz;
        wza[j] = 1.f - fz;
    }

    #pragma unroll
    for (int i = 0; i < 2; i++) {
        int col = wq + 8 * i;
        const uint2* P = S_plane + col * ROWE;
        float4 g4 = (i == 0) ? gv0 : gv1;
        float tg[4] = { g4.x, g4.y, g4.z, g4.w };

        float acc[4][4];
        #pragma unroll
        for (int j = 0; j < 4; j++) {
            float t = fminf(fmaxf(tg[j] * 15.0f, 0.0f), 15.0f);
            float t0f = floorf(t);
            float ft = t - t0f;
            int t0 = (int)t0f;
            int t1 = min(t0 + 1, UP - 1);

            uint2 e00 = P[z0o[j] + t0];
            uint2 e01 = P[z0o[j] + t1];
            uint2 e10 = P[z1o[j] + t0];
            uint2 e11 = P[z1o[j] + t1];

            float w00 = wza[j] * (1.f - ft);
            float w01 = wza[j] * ft;
            float w10 = fzv[j] * (1.f - ft);
            float w11 = fzv[j] * ft;

            float2 p01, p23;
            p01 = __half22float2(u2h(e00.x)); p23 = __half22float2(u2h(e00.y));
            acc[j][0] = p01.x * w00; acc[j][1] = p01.y * w00;
            acc[j][2] = p23.x * w00; acc[j][3] = p23.y * w00;
            p01 = __half22float2(u2h(e01.x)); p23 = __half22float2(u2h(e01.y));
            acc[j][0] = fmaf(p01.x, w01, acc[j][0]); acc[j][1] = fmaf(p01.y, w01, acc[j][1]);
            acc[j][2] = fmaf(p23.x, w01, acc[j][2]); acc[j][3] = fmaf(p23.y, w01, acc[j][3]);
            p01 = __half22float2(u2h(e10.x)); p23 = __half22float2(u2h(e10.y));
            acc[j][0] = fmaf(p01.x, w10, acc[j][0]); acc[j][1] = fmaf(p01.y, w10, acc[j][1]);
            acc[j][2] = fmaf(p23.x, w10, acc[j][2]); acc[j][3] = fmaf(p23.y, w10, acc[j][3]);
            p01 = __half22float2(u2h(e11.x)); p23 = __half22float2(u2h(e11.y));
            acc[j][0] = fmaf(p01.x, w11, acc[j][0]); acc[j][1] = fmaf(p01.y, w11, acc[j][1]);
            acc[j][2] = fmaf(p23.x, w11, acc[j][2]); acc[j][3] = fmaf(p23.y, w11, acc[j][3]);
        }

        #pragma unroll
        for (int c = 0; c < 4; c++) {
            float4 o = make_float4(acc[0][c], acc[1][c], acc[2][c], acc[3][c]);
            *reinterpret_cast<float4*>(&out[obase[i] + c * OUT_CH]) = o;
        }
    }
}

extern "C" void kernel_launch(void* const* d_in, const int* in_sizes, int n_in,
                              void* d_out, int out_size)
{
    const float* bg = (const float*)d_in[0];
    const float* gm = (const float*)d_in[1];
    float* out = (float*)d_out;

    cudaFuncSetAttribute(bgrid_slice_kernel,
                         cudaFuncAttributeMaxDynamicSharedMemorySize, PLANE_BYTES);

    dim3 grid(GWD / TW, GH / TH);   // 32 x 32 = 1024 blocks
    bgrid_slice_kernel<<<grid, 256, PLANE_BYTES>>>(bg, gm, out);
}